// round 1
// baseline (speedup 1.0000x reference)
#include <cuda_runtime.h>
#include <cuda_bf16.h>
#include <cstdint>
#include <cstdio>

// ---------------------------------------------------------------------------
// Problem constants (shapes fixed by the dataset)
//   N0 = N1 = 50000, D0 = 256, D1 = 512, DO = 256, E = 1600000
// ---------------------------------------------------------------------------
#define MAX_N   50000
#define MAX_E   1600000
#define DO_DIM  256
#define LN_EPS  1e-5f

// ---------------------------------------------------------------------------
// Device scratch (static — no allocations allowed)
// ---------------------------------------------------------------------------
__device__ float g_hproj0[MAX_N * DO_DIM];   // x0 @ W0
__device__ float g_hproj1[MAX_N * DO_DIM];   // x1 @ W1
__device__ float g_res1  [MAX_N * DO_DIM];   // x1 @ Wres1

__device__ int   g_cnt0[MAX_N],  g_cnt1[MAX_N];
__device__ int   g_off0[MAX_N],  g_off1[MAX_N];
__device__ int   g_cur0[MAX_N],  g_cur1[MAX_N];
__device__ int2  g_edge0[MAX_E], g_edge1[MAX_E];   // {col, bit-cast ew}

// ---------------------------------------------------------------------------
// SGEMM: C[M,N] = A[M,K] @ B[K,N], fp32, 128x128 block tile, 8x8 per thread
// Requires: K % 8 == 0, N % 128 == 0 (true here: K in {256,512}, N=256)
// ---------------------------------------------------------------------------
__global__ __launch_bounds__(256)
void sgemm_kernel(const float* __restrict__ A, const float* __restrict__ B,
                  float* __restrict__ C, int M, int K, int N)
{
    __shared__ float As[8][128];
    __shared__ float Bs[8][128];

    const int tid = threadIdx.x;
    const int tx  = tid & 15;        // 0..15  (N direction)
    const int ty  = tid >> 4;        // 0..15  (M direction)
    const int row0 = blockIdx.y * 128;
    const int col0 = blockIdx.x * 128;

    // A-tile load mapping: 128 rows x 8 k -> 256 threads x float4
    const int a_row = tid >> 1;            // 0..127
    const int a_col = (tid & 1) * 4;       // 0 or 4
    // B-tile load mapping: 8 k x 128 n -> 256 threads x float4
    const int b_row = tid >> 5;            // 0..7
    const int b_col = (tid & 31) * 4;      // 0..124

    float acc[8][8];
    #pragma unroll
    for (int i = 0; i < 8; i++)
        #pragma unroll
        for (int j = 0; j < 8; j++) acc[i][j] = 0.f;

    for (int k0 = 0; k0 < K; k0 += 8) {
        // load A tile (guard M), store transposed As[k][m]
        float4 av = make_float4(0.f, 0.f, 0.f, 0.f);
        const int gr = row0 + a_row;
        if (gr < M)
            av = *reinterpret_cast<const float4*>(&A[(size_t)gr * K + k0 + a_col]);
        As[a_col + 0][a_row] = av.x;
        As[a_col + 1][a_row] = av.y;
        As[a_col + 2][a_row] = av.z;
        As[a_col + 3][a_row] = av.w;

        // load B tile
        float4 bv = *reinterpret_cast<const float4*>(
            &B[(size_t)(k0 + b_row) * N + col0 + b_col]);
        *reinterpret_cast<float4*>(&Bs[b_row][b_col]) = bv;

        __syncthreads();

        #pragma unroll
        for (int k = 0; k < 8; k++) {
            float4 a0 = *reinterpret_cast<const float4*>(&As[k][ty * 8]);
            float4 a1 = *reinterpret_cast<const float4*>(&As[k][ty * 8 + 4]);
            float4 b0 = *reinterpret_cast<const float4*>(&Bs[k][tx * 8]);
            float4 b1 = *reinterpret_cast<const float4*>(&Bs[k][tx * 8 + 4]);
            float ar[8] = {a0.x, a0.y, a0.z, a0.w, a1.x, a1.y, a1.z, a1.w};
            float br[8] = {b0.x, b0.y, b0.z, b0.w, b1.x, b1.y, b1.z, b1.w};
            #pragma unroll
            for (int i = 0; i < 8; i++)
                #pragma unroll
                for (int j = 0; j < 8; j++)
                    acc[i][j] += ar[i] * br[j];
        }
        __syncthreads();
    }

    #pragma unroll
    for (int i = 0; i < 8; i++) {
        const int r = row0 + ty * 8 + i;
        if (r < M) {
            float4 v0 = make_float4(acc[i][0], acc[i][1], acc[i][2], acc[i][3]);
            float4 v1 = make_float4(acc[i][4], acc[i][5], acc[i][6], acc[i][7]);
            float* cp = &C[(size_t)r * N + col0 + tx * 8];
            *reinterpret_cast<float4*>(cp)     = v0;
            *reinterpret_cast<float4*>(cp + 4) = v1;
        }
    }
}

// ---------------------------------------------------------------------------
// CSR construction
// ---------------------------------------------------------------------------
__global__ void zero_counts_kernel(int* __restrict__ c0, int* __restrict__ c1, int n)
{
    int i = blockIdx.x * blockDim.x + threadIdx.x;
    if (i < n) { c0[i] = 0; c1[i] = 0; }
}

__global__ void hist_kernel(const int* __restrict__ row, int e, int* __restrict__ cnt)
{
    int i = blockIdx.x * blockDim.x + threadIdx.x;
    if (i < e) atomicAdd(&cnt[row[i]], 1);
}

// Single-block exclusive scan over n counts -> offs and cursor (copy).
__global__ __launch_bounds__(1024)
void scan_kernel(const int* __restrict__ cnt, int* __restrict__ offs,
                 int* __restrict__ cursor, int n)
{
    __shared__ int ws[32];
    const int tid  = threadIdx.x;
    const int lane = tid & 31;
    const int wid  = tid >> 5;
    int carry = 0;

    for (int base = 0; base < n; base += 1024) {
        const int idx = base + tid;
        int v = (idx < n) ? cnt[idx] : 0;
        // inclusive warp scan
        int x = v;
        #pragma unroll
        for (int d = 1; d < 32; d <<= 1) {
            int y = __shfl_up_sync(0xffffffffu, x, d);
            if (lane >= d) x += y;
        }
        if (lane == 31) ws[wid] = x;
        __syncthreads();
        if (wid == 0) {
            int y = ws[lane];
            #pragma unroll
            for (int d = 1; d < 32; d <<= 1) {
                int z = __shfl_up_sync(0xffffffffu, y, d);
                if (lane >= d) y += z;
            }
            ws[lane] = y;
        }
        __syncthreads();
        const int warp_off = (wid > 0) ? ws[wid - 1] : 0;
        const int excl = carry + warp_off + x - v;
        if (idx < n) { offs[idx] = excl; cursor[idx] = excl; }
        carry += ws[31];           // block total (every thread reads it)
        __syncthreads();           // protect ws before next iteration rewrites
    }
}

__global__ void scatter_kernel(const int* __restrict__ row, const int* __restrict__ col,
                               const float* __restrict__ ew, int e,
                               int* __restrict__ cursor, int2* __restrict__ edges)
{
    int i = blockIdx.x * blockDim.x + threadIdx.x;
    if (i < e) {
        const int r = row[i];
        const int p = atomicAdd(&cursor[r], 1);
        edges[p] = make_int2(col[i], __float_as_int(ew[i]));
    }
}

// ---------------------------------------------------------------------------
// Aggregation + fused LayerNorm. One warp per output row (DO = 256).
// acc initialized from residual; edges gathered from L2-resident h_proj.
// ---------------------------------------------------------------------------
__global__ __launch_bounds__(256)
void aggregate_ln_kernel(const float* __restrict__ hproj,
                         const float* __restrict__ resid,
                         const int*   __restrict__ offs,
                         const int*   __restrict__ cnt,
                         const int2*  __restrict__ edges,
                         const float* __restrict__ gamma,
                         const float* __restrict__ beta,
                         float* __restrict__ out, int nrows)
{
    const int warp_id = (blockIdx.x * blockDim.x + threadIdx.x) >> 5;
    if (warp_id >= nrows) return;
    const int lane   = threadIdx.x & 31;
    const int base_c = lane * 8;

    const int start = offs[warp_id];
    const int n     = cnt[warp_id];

    const float4* rp = reinterpret_cast<const float4*>(
        resid + (size_t)warp_id * DO_DIM + base_c);
    float4 a0 = rp[0];
    float4 a1 = rp[1];

    for (int e = 0; e < n; e++) {
        const int2 ed = edges[start + e];
        const float w = __int_as_float(ed.y);
        const float4* hp = reinterpret_cast<const float4*>(
            hproj + (size_t)ed.x * DO_DIM + base_c);
        const float4 h0 = hp[0];
        const float4 h1 = hp[1];
        a0.x += w * h0.x; a0.y += w * h0.y; a0.z += w * h0.z; a0.w += w * h0.w;
        a1.x += w * h1.x; a1.y += w * h1.y; a1.z += w * h1.z; a1.w += w * h1.w;
    }

    // LayerNorm over 256 columns (warp reduce)
    float s  = a0.x + a0.y + a0.z + a0.w + a1.x + a1.y + a1.z + a1.w;
    float s2 = a0.x*a0.x + a0.y*a0.y + a0.z*a0.z + a0.w*a0.w
             + a1.x*a1.x + a1.y*a1.y + a1.z*a1.z + a1.w*a1.w;
    #pragma unroll
    for (int d = 16; d > 0; d >>= 1) {
        s  += __shfl_xor_sync(0xffffffffu, s,  d);
        s2 += __shfl_xor_sync(0xffffffffu, s2, d);
    }
    const float mu  = s * (1.f / DO_DIM);
    const float var = s2 * (1.f / DO_DIM) - mu * mu;
    const float inv = rsqrtf(var + LN_EPS);

    const float4 gv0 = *reinterpret_cast<const float4*>(&gamma[base_c]);
    const float4 gv1 = *reinterpret_cast<const float4*>(&gamma[base_c + 4]);
    const float4 bv0 = *reinterpret_cast<const float4*>(&beta [base_c]);
    const float4 bv1 = *reinterpret_cast<const float4*>(&beta [base_c + 4]);

    float4 o0, o1;
    o0.x = (a0.x - mu) * inv * gv0.x + bv0.x;
    o0.y = (a0.y - mu) * inv * gv0.y + bv0.y;
    o0.z = (a0.z - mu) * inv * gv0.z + bv0.z;
    o0.w = (a0.w - mu) * inv * gv0.w + bv0.w;
    o1.x = (a1.x - mu) * inv * gv1.x + bv1.x;
    o1.y = (a1.y - mu) * inv * gv1.y + bv1.y;
    o1.z = (a1.z - mu) * inv * gv1.z + bv1.z;
    o1.w = (a1.w - mu) * inv * gv1.w + bv1.w;

    float* op = out + (size_t)warp_id * DO_DIM + base_c;
    *reinterpret_cast<float4*>(op)     = o0;
    *reinterpret_cast<float4*>(op + 4) = o1;
}

// ---------------------------------------------------------------------------
// Launch
// ---------------------------------------------------------------------------
extern "C" void kernel_launch(void* const* d_in, const int* in_sizes, int n_in,
                              void* d_out, int out_size)
{
    const float* x0    = (const float*)d_in[0];
    const float* x1    = (const float*)d_in[1];
    const float* W0    = (const float*)d_in[2];
    const float* W1    = (const float*)d_in[3];
    const float* Wres1 = (const float*)d_in[4];
    const float* g0    = (const float*)d_in[5];
    const float* b0    = (const float*)d_in[6];
    const float* g1    = (const float*)d_in[7];
    const float* b1    = (const float*)d_in[8];
    const float* ew0   = (const float*)d_in[9];
    const float* ew1   = (const float*)d_in[10];
    const int*   row0  = (const int*)d_in[11];
    const int*   col0  = (const int*)d_in[12];
    const int*   row1  = (const int*)d_in[13];
    const int*   col1  = (const int*)d_in[14];
    float* out = (float*)d_out;

    const int D0 = 256, D1 = 512, DO = DO_DIM;
    const int N0 = in_sizes[0] / D0;      // 50000
    const int N1 = in_sizes[1] / D1;      // 50000
    const int E  = in_sizes[9];           // 1600000

    // scratch pointers
    float *hproj0, *hproj1, *res1;
    int *cnt0, *cnt1, *off0, *off1, *cur0, *cur1;
    int2 *edge0, *edge1;
    cudaGetSymbolAddress((void**)&hproj0, g_hproj0);
    cudaGetSymbolAddress((void**)&hproj1, g_hproj1);
    cudaGetSymbolAddress((void**)&res1,   g_res1);
    cudaGetSymbolAddress((void**)&cnt0,   g_cnt0);
    cudaGetSymbolAddress((void**)&cnt1,   g_cnt1);
    cudaGetSymbolAddress((void**)&off0,   g_off0);
    cudaGetSymbolAddress((void**)&off1,   g_off1);
    cudaGetSymbolAddress((void**)&cur0,   g_cur0);
    cudaGetSymbolAddress((void**)&cur1,   g_cur1);
    cudaGetSymbolAddress((void**)&edge0,  g_edge0);
    cudaGetSymbolAddress((void**)&edge1,  g_edge1);

    // --- CSR build ---
    {
        const int nb = (N0 > N1 ? N0 : N1);
        zero_counts_kernel<<<(nb + 255) / 256, 256>>>(cnt0, cnt1, nb);
    }
    hist_kernel<<<(E + 255) / 256, 256>>>(row0, E, cnt0);
    hist_kernel<<<(E + 255) / 256, 256>>>(row1, E, cnt1);
    scan_kernel<<<1, 1024>>>(cnt0, off0, cur0, N0);
    scan_kernel<<<1, 1024>>>(cnt1, off1, cur1, N1);
    scatter_kernel<<<(E + 255) / 256, 256>>>(row0, col0, ew0, E, cur0, edge0);
    scatter_kernel<<<(E + 255) / 256, 256>>>(row1, col1, ew1, E, cur1, edge1);

    // --- dense projections ---
    {
        dim3 blk(256);
        dim3 grid0(DO / 128, (N0 + 127) / 128);
        sgemm_kernel<<<grid0, blk>>>(x0, W0, hproj0, N0, D0, DO);
        dim3 grid1(DO / 128, (N1 + 127) / 128);
        sgemm_kernel<<<grid1, blk>>>(x1, W1,    hproj1, N1, D1, DO);
        sgemm_kernel<<<grid1, blk>>>(x1, Wres1, res1,   N1, D1, DO);
    }

    // --- aggregate + layernorm (one warp per row) ---
    {
        const int warps_per_block = 256 / 32;
        const int nb0 = (N0 + warps_per_block - 1) / warps_per_block;
        const int nb1 = (N1 + warps_per_block - 1) / warps_per_block;
        aggregate_ln_kernel<<<nb0, 256>>>(hproj0, x0,   off0, cnt0, edge0,
                                          g0, b0, out, N0);
        aggregate_ln_kernel<<<nb1, 256>>>(hproj1, res1, off1, cnt1, edge1,
                                          g1, b1, out + (size_t)N0 * DO_DIM, N1);
    }
}

// round 3
// speedup vs baseline: 1.5468x; 1.5468x over previous
#include <cuda_runtime.h>
#include <cuda_bf16.h>
#include <cstdint>

// ---------------------------------------------------------------------------
// Shapes: N0 = N1 = 50000, D0 = 256, D1 = 512, DO = 256, E = 1600000
// ---------------------------------------------------------------------------
#define MAX_N   50000
#define MAX_E   1600000
#define DO_DIM  256
#define LN_EPS  1e-5f

// ---------------------------------------------------------------------------
// Device scratch (static — no allocations allowed)
// ---------------------------------------------------------------------------
__device__ float g_hproj0[MAX_N * DO_DIM];
__device__ float g_hproj1[MAX_N * DO_DIM];
__device__ float g_res1  [MAX_N * DO_DIM];

__device__ int   g_cnt0[MAX_N],  g_cnt1[MAX_N];
__device__ int   g_off0[MAX_N],  g_off1[MAX_N];
__device__ int   g_cur0[MAX_N],  g_cur1[MAX_N];
__device__ int2  g_edge0[MAX_E], g_edge1[MAX_E];

// bf16 hi/lo splits of activations, [M][K] row-major
__device__ __align__(16) __nv_bfloat16 g_x0hi[MAX_N * 256], g_x0lo[MAX_N * 256];
__device__ __align__(16) __nv_bfloat16 g_x1hi[MAX_N * 512], g_x1lo[MAX_N * 512];
// W transposed + split: [N=256][K] row-major
__device__ __align__(16) __nv_bfloat16 g_w0_hi[256 * 256], g_w0_lo[256 * 256];
__device__ __align__(16) __nv_bfloat16 g_w1_hi[256 * 512], g_w1_lo[256 * 512];
__device__ __align__(16) __nv_bfloat16 g_wr_hi[256 * 512], g_wr_lo[256 * 512];

// ---------------------------------------------------------------------------
// PTX helpers — only non-suffixed instructions (compute_103-safe)
// ---------------------------------------------------------------------------
__device__ __forceinline__ uint32_t smem_u32(const void* p) {
    uint32_t a;
    asm("{ .reg .u64 t; cvta.to.shared.u64 t, %1; cvt.u32.u64 %0, t; }"
        : "=r"(a) : "l"(p));
    return a;
}

#define LDSM_X4(r0, r1, r2, r3, addr)                                        \
    asm volatile("ldmatrix.sync.aligned.m8n8.x4.shared.b16 {%0,%1,%2,%3}, [%4];" \
        : "=r"(r0), "=r"(r1), "=r"(r2), "=r"(r3) : "r"(addr))

#define MMA_BF16(d, a0, a1, a2, a3, b0, b1)                                  \
    asm volatile("mma.sync.aligned.m16n8k16.row.col.f32.bf16.bf16.f32 "      \
        "{%0,%1,%2,%3},{%4,%5,%6,%7},{%8,%9},{%0,%1,%2,%3};"                 \
        : "+f"((d)[0]), "+f"((d)[1]), "+f"((d)[2]), "+f"((d)[3])             \
        : "r"(a0), "r"(a1), "r"(a2), "r"(a3), "r"(b0), "r"(b1))

// ---------------------------------------------------------------------------
// HMMA bf16-split GEMM.
//   C[j][M,256] = A[M,K](fp32, pre-split hi/lo) @ W[j]^T   (W^T pre-split)
//   3-term compensated product: Ahi*Bhi + Ahi*Blo + Alo*Bhi
// Block: 128(M) x 64(N), K-chunk 32, double-buffered smem, 8 warps @ 32x32.
// NB = number of B matrices / outputs (1 or 2).
// ---------------------------------------------------------------------------
template <int NB>
__global__ __launch_bounds__(256)
void hmma_gemm(const __nv_bfloat16* __restrict__ Ahi,
               const __nv_bfloat16* __restrict__ Alo,
               const __nv_bfloat16* __restrict__ B0h,
               const __nv_bfloat16* __restrict__ B0l,
               const __nv_bfloat16* __restrict__ B1h,
               const __nv_bfloat16* __restrict__ B1l,
               float* __restrict__ C0, float* __restrict__ C1,
               int M, int K)
{
    constexpr int APAD = 40;                     // 32 cols + 8 pad (80B rows)
    __shared__ __align__(16) __nv_bfloat16 sA[2][128 * APAD];
    __shared__ __align__(16) __nv_bfloat16 sB[2][NB * 64 * APAD];

    const int tid  = threadIdx.x;
    const int lane = tid & 31;
    const int wid  = tid >> 5;
    const int wm   = wid >> 1;                   // 0..3  (M)
    const int wn   = wid & 1;                    // 0..1  (N)
    const int row0 = blockIdx.y * 128;
    const int col0 = blockIdx.x * 64;

    const int kpt = K >> 5;                      // chunks per term
    const int NC  = 3 * kpt;

    const __nv_bfloat16* Bh[2] = {B0h, B1h};
    const __nv_bfloat16* Bl[2] = {B0l, B1l};

    float acc[NB][2][4][4];
    #pragma unroll
    for (int jj = 0; jj < NB; jj++)
        #pragma unroll
        for (int i = 0; i < 2; i++)
            #pragma unroll
            for (int q = 0; q < 4; q++)
                #pragma unroll
                for (int v = 0; v < 4; v++) acc[jj][i][q][v] = 0.f;

    // global-load staging registers
    uint4 ra[2], rb[NB];
    const int a_r = tid >> 2;                    // 0..63
    const int a_g = tid & 3;                     // 16B granule

    auto gload = [&](int c) {
        const int t  = c / kpt;
        const int kk = (c - t * kpt) << 5;
        const __nv_bfloat16* As = (t == 2) ? Alo : Ahi;
        #pragma unroll
        for (int i = 0; i < 2; i++) {
            const int gr = row0 + i * 64 + a_r;
            ra[i] = make_uint4(0u, 0u, 0u, 0u);
            if (gr < M)
                ra[i] = *reinterpret_cast<const uint4*>(
                    &As[(size_t)gr * K + kk + a_g * 8]);
        }
        #pragma unroll
        for (int j = 0; j < NB; j++) {
            const __nv_bfloat16* Bs = (t == 1) ? Bl[j] : Bh[j];
            rb[j] = *reinterpret_cast<const uint4*>(
                &Bs[(size_t)(col0 + a_r) * K + kk + a_g * 8]);
        }
    };
    auto sstore = [&](int buf) {
        #pragma unroll
        for (int i = 0; i < 2; i++)
            *reinterpret_cast<uint4*>(&sA[buf][(i * 64 + a_r) * APAD + a_g * 8]) = ra[i];
        #pragma unroll
        for (int j = 0; j < NB; j++)
            *reinterpret_cast<uint4*>(&sB[buf][(j * 64 + a_r) * APAD + a_g * 8]) = rb[j];
    };

    const uint32_t sA_u = smem_u32(&sA[0][0]);
    const uint32_t sB_u = smem_u32(&sB[0][0]);
    constexpr uint32_t A_BUF = 128 * APAD * 2;
    constexpr uint32_t B_BUF = NB * 64 * APAD * 2;

    auto compute = [&](int buf) {
        #pragma unroll
        for (int j = 0; j < 2; j++) {            // two k16 in a 32-chunk
            uint32_t af[2][4];
            #pragma unroll
            for (int i = 0; i < 2; i++) {
                const uint32_t addr = sA_u + buf * A_BUF +
                    2u * ((wm * 32 + i * 16 + (lane & 15)) * APAD +
                          j * 16 + (lane >> 4) * 8);
                LDSM_X4(af[i][0], af[i][1], af[i][2], af[i][3], addr);
            }
            #pragma unroll
            for (int jj = 0; jj < NB; jj++) {
                uint32_t bfr[2][4];
                #pragma unroll
                for (int p = 0; p < 2; p++) {
                    const uint32_t addr = sB_u + buf * B_BUF +
                        2u * ((jj * 64 + wn * 32 + p * 16 + (lane & 15)) * APAD +
                              j * 16 + (lane >> 4) * 8);
                    LDSM_X4(bfr[p][0], bfr[p][1], bfr[p][2], bfr[p][3], addr);
                }
                #pragma unroll
                for (int i = 0; i < 2; i++)
                    #pragma unroll
                    for (int q = 0; q < 4; q++) {
                        const int p = q >> 1, s = q & 1;
                        MMA_BF16(acc[jj][i][q],
                                 af[i][0], af[i][1], af[i][2], af[i][3],
                                 bfr[p][s], bfr[p][s + 2]);
                    }
            }
        }
    };

    gload(0);
    sstore(0);
    __syncthreads();

    for (int c = 0; c < NC; c++) {
        const int cur = c & 1;
        const bool has_next = (c + 1 < NC);
        if (has_next) gload(c + 1);
        compute(cur);
        if (has_next) {
            sstore(cur ^ 1);
            __syncthreads();
        }
    }

    // ---- epilogue: write fp32 C ----
    #pragma unroll
    for (int jj = 0; jj < NB; jj++) {
        float* Cp = (jj == 0) ? C0 : C1;
        #pragma unroll
        for (int i = 0; i < 2; i++) {
            const int r = row0 + wm * 32 + i * 16 + (lane >> 2);
            #pragma unroll
            for (int q = 0; q < 4; q++) {
                const int cc = col0 + wn * 32 + q * 8 + (lane & 3) * 2;
                if (r < M) {
                    float2 v = make_float2(acc[jj][i][q][0], acc[jj][i][q][1]);
                    *reinterpret_cast<float2*>(&Cp[(size_t)r * DO_DIM + cc]) = v;
                }
                if (r + 8 < M) {
                    float2 v = make_float2(acc[jj][i][q][2], acc[jj][i][q][3]);
                    *reinterpret_cast<float2*>(&Cp[(size_t)(r + 8) * DO_DIM + cc]) = v;
                }
            }
        }
    }
}

// ---------------------------------------------------------------------------
// Split conversions
// ---------------------------------------------------------------------------
__global__ void convert_x_kernel(const float* __restrict__ x, int n4,
                                 __nv_bfloat16* __restrict__ hi,
                                 __nv_bfloat16* __restrict__ lo)
{
    const int i = blockIdx.x * blockDim.x + threadIdx.x;
    if (i >= n4) return;
    const float4 v = *reinterpret_cast<const float4*>(&x[(size_t)i * 4]);
    __nv_bfloat16 h[4], l[4];
    const float f[4] = {v.x, v.y, v.z, v.w};
    #pragma unroll
    for (int k = 0; k < 4; k++) {
        h[k] = __float2bfloat16(f[k]);
        l[k] = __float2bfloat16(f[k] - __bfloat162float(h[k]));
    }
    uint2 hv, lv;
    hv.x = ((uint32_t)__bfloat16_as_ushort(h[1]) << 16) | __bfloat16_as_ushort(h[0]);
    hv.y = ((uint32_t)__bfloat16_as_ushort(h[3]) << 16) | __bfloat16_as_ushort(h[2]);
    lv.x = ((uint32_t)__bfloat16_as_ushort(l[1]) << 16) | __bfloat16_as_ushort(l[0]);
    lv.y = ((uint32_t)__bfloat16_as_ushort(l[3]) << 16) | __bfloat16_as_ushort(l[2]);
    *reinterpret_cast<uint2*>(&hi[(size_t)i * 4]) = hv;
    *reinterpret_cast<uint2*>(&lo[(size_t)i * 4]) = lv;
}

// W [K][256] fp32 -> W^T hi/lo [256][K] bf16
__global__ void convert_w_kernel(const float* __restrict__ W, int K,
                                 __nv_bfloat16* __restrict__ hi,
                                 __nv_bfloat16* __restrict__ lo)
{
    const int idx = blockIdx.x * blockDim.x + threadIdx.x;
    if (idx >= 256 * K) return;
    const int n = idx & 255;
    const int k = idx >> 8;
    const float v = W[(size_t)k * 256 + n];
    const __nv_bfloat16 h = __float2bfloat16(v);
    hi[(size_t)n * K + k] = h;
    lo[(size_t)n * K + k] = __float2bfloat16(v - __bfloat162float(h));
}

// ---------------------------------------------------------------------------
// CSR construction
// ---------------------------------------------------------------------------
__global__ void zero_counts_kernel(int* __restrict__ c0, int* __restrict__ c1, int n)
{
    int i = blockIdx.x * blockDim.x + threadIdx.x;
    if (i < n) { c0[i] = 0; c1[i] = 0; }
}

__global__ void hist_kernel(const int* __restrict__ row, int e, int* __restrict__ cnt)
{
    int i = blockIdx.x * blockDim.x + threadIdx.x;
    if (i < e) atomicAdd(&cnt[row[i]], 1);
}

__global__ __launch_bounds__(1024)
void scan2_kernel(const int* __restrict__ cA, int* __restrict__ oA, int* __restrict__ uA,
                  const int* __restrict__ cB, int* __restrict__ oB, int* __restrict__ uB,
                  int n)
{
    const int* cnt = blockIdx.x ? cB : cA;
    int* offs      = blockIdx.x ? oB : oA;
    int* cursor    = blockIdx.x ? uB : uA;

    __shared__ int ws[32];
    const int tid  = threadIdx.x;
    const int lane = tid & 31;
    const int wid  = tid >> 5;
    int carry = 0;

    for (int base = 0; base < n; base += 1024) {
        const int idx = base + tid;
        int v = (idx < n) ? cnt[idx] : 0;
        int x = v;
        #pragma unroll
        for (int d = 1; d < 32; d <<= 1) {
            int y = __shfl_up_sync(0xffffffffu, x, d);
            if (lane >= d) x += y;
        }
        if (lane == 31) ws[wid] = x;
        __syncthreads();
        if (wid == 0) {
            int y = ws[lane];
            #pragma unroll
            for (int d = 1; d < 32; d <<= 1) {
                int z = __shfl_up_sync(0xffffffffu, y, d);
                if (lane >= d) y += z;
            }
            ws[lane] = y;
        }
        __syncthreads();
        const int warp_off = (wid > 0) ? ws[wid - 1] : 0;
        const int excl = carry + warp_off + x - v;
        if (idx < n) { offs[idx] = excl; cursor[idx] = excl; }
        carry += ws[31];
        __syncthreads();
    }
}

__global__ void scatter_kernel(const int* __restrict__ row, const int* __restrict__ col,
                               const float* __restrict__ ew, int e,
                               int* __restrict__ cursor, int2* __restrict__ edges)
{
    int i = blockIdx.x * blockDim.x + threadIdx.x;
    if (i < e) {
        const int r = row[i];
        const int p = atomicAdd(&cursor[r], 1);
        edges[p] = make_int2(col[i], __float_as_int(ew[i]));
    }
}

// ---------------------------------------------------------------------------
// Aggregation + fused LayerNorm. One warp per output row (DO = 256).
// ---------------------------------------------------------------------------
__global__ __launch_bounds__(256)
void aggregate_ln_kernel(const float* __restrict__ hproj,
                         const float* __restrict__ resid,
                         const int*   __restrict__ offs,
                         const int*   __restrict__ cnt,
                         const int2*  __restrict__ edges,
                         const float* __restrict__ gamma,
                         const float* __restrict__ beta,
                         float* __restrict__ out, int nrows)
{
    const int warp_id = (blockIdx.x * blockDim.x + threadIdx.x) >> 5;
    if (warp_id >= nrows) return;
    const int lane   = threadIdx.x & 31;
    const int base_c = lane * 8;

    const int start = offs[warp_id];
    const int n     = cnt[warp_id];

    const float4* rp = reinterpret_cast<const float4*>(
        resid + (size_t)warp_id * DO_DIM + base_c);
    float4 a0 = rp[0];
    float4 a1 = rp[1];

    for (int e = 0; e < n; e++) {
        const int2 ed = edges[start + e];
        const float w = __int_as_float(ed.y);
        const float4* hp = reinterpret_cast<const float4*>(
            hproj + (size_t)ed.x * DO_DIM + base_c);
        const float4 h0 = hp[0];
        const float4 h1 = hp[1];
        a0.x += w * h0.x; a0.y += w * h0.y; a0.z += w * h0.z; a0.w += w * h0.w;
        a1.x += w * h1.x; a1.y += w * h1.y; a1.z += w * h1.z; a1.w += w * h1.w;
    }

    float s  = a0.x + a0.y + a0.z + a0.w + a1.x + a1.y + a1.z + a1.w;
    float s2 = a0.x*a0.x + a0.y*a0.y + a0.z*a0.z + a0.w*a0.w
             + a1.x*a1.x + a1.y*a1.y + a1.z*a1.z + a1.w*a1.w;
    #pragma unroll
    for (int d = 16; d > 0; d >>= 1) {
        s  += __shfl_xor_sync(0xffffffffu, s,  d);
        s2 += __shfl_xor_sync(0xffffffffu, s2, d);
    }
    const float mu  = s * (1.f / DO_DIM);
    const float var = s2 * (1.f / DO_DIM) - mu * mu;
    const float inv = rsqrtf(var + LN_EPS);

    const float4 gv0 = *reinterpret_cast<const float4*>(&gamma[base_c]);
    const float4 gv1 = *reinterpret_cast<const float4*>(&gamma[base_c + 4]);
    const float4 bv0 = *reinterpret_cast<const float4*>(&beta [base_c]);
    const float4 bv1 = *reinterpret_cast<const float4*>(&beta [base_c + 4]);

    float4 o0, o1;
    o0.x = (a0.x - mu) * inv * gv0.x + bv0.x;
    o0.y = (a0.y - mu) * inv * gv0.y + bv0.y;
    o0.z = (a0.z - mu) * inv * gv0.z + bv0.z;
    o0.w = (a0.w - mu) * inv * gv0.w + bv0.w;
    o1.x = (a1.x - mu) * inv * gv1.x + bv1.x;
    o1.y = (a1.y - mu) * inv * gv1.y + bv1.y;
    o1.z = (a1.z - mu) * inv * gv1.z + bv1.z;
    o1.w = (a1.w - mu) * inv * gv1.w + bv1.w;

    float* op = out + (size_t)warp_id * DO_DIM + base_c;
    *reinterpret_cast<float4*>(op)     = o0;
    *reinterpret_cast<float4*>(op + 4) = o1;
}

// ---------------------------------------------------------------------------
// Launch
// ---------------------------------------------------------------------------
extern "C" void kernel_launch(void* const* d_in, const int* in_sizes, int n_in,
                              void* d_out, int out_size)
{
    const float* x0    = (const float*)d_in[0];
    const float* x1    = (const float*)d_in[1];
    const float* W0    = (const float*)d_in[2];
    const float* W1    = (const float*)d_in[3];
    const float* Wres1 = (const float*)d_in[4];
    const float* g0    = (const float*)d_in[5];
    const float* b0    = (const float*)d_in[6];
    const float* g1    = (const float*)d_in[7];
    const float* b1    = (const float*)d_in[8];
    const float* ew0   = (const float*)d_in[9];
    const float* ew1   = (const float*)d_in[10];
    const int*   row0  = (const int*)d_in[11];
    const int*   col0  = (const int*)d_in[12];
    const int*   row1  = (const int*)d_in[13];
    const int*   col1  = (const int*)d_in[14];
    float* out = (float*)d_out;

    const int D0 = 256, D1 = 512;
    const int N0 = in_sizes[0] / D0;
    const int N1 = in_sizes[1] / D1;
    const int E  = in_sizes[9];

    float *hproj0, *hproj1, *res1;
    int *cnt0, *cnt1, *off0, *off1, *cur0, *cur1;
    int2 *edge0, *edge1;
    __nv_bfloat16 *x0h, *x0l, *x1h, *x1l;
    __nv_bfloat16 *w0h, *w0l, *w1h, *w1l, *wrh, *wrl;
    cudaGetSymbolAddress((void**)&hproj0, g_hproj0);
    cudaGetSymbolAddress((void**)&hproj1, g_hproj1);
    cudaGetSymbolAddress((void**)&res1,   g_res1);
    cudaGetSymbolAddress((void**)&cnt0,   g_cnt0);
    cudaGetSymbolAddress((void**)&cnt1,   g_cnt1);
    cudaGetSymbolAddress((void**)&off0,   g_off0);
    cudaGetSymbolAddress((void**)&off1,   g_off1);
    cudaGetSymbolAddress((void**)&cur0,   g_cur0);
    cudaGetSymbolAddress((void**)&cur1,   g_cur1);
    cudaGetSymbolAddress((void**)&edge0,  g_edge0);
    cudaGetSymbolAddress((void**)&edge1,  g_edge1);
    cudaGetSymbolAddress((void**)&x0h,    g_x0hi);
    cudaGetSymbolAddress((void**)&x0l,    g_x0lo);
    cudaGetSymbolAddress((void**)&x1h,    g_x1hi);
    cudaGetSymbolAddress((void**)&x1l,    g_x1lo);
    cudaGetSymbolAddress((void**)&w0h,    g_w0_hi);
    cudaGetSymbolAddress((void**)&w0l,    g_w0_lo);
    cudaGetSymbolAddress((void**)&w1h,    g_w1_hi);
    cudaGetSymbolAddress((void**)&w1l,    g_w1_lo);
    cudaGetSymbolAddress((void**)&wrh,    g_wr_hi);
    cudaGetSymbolAddress((void**)&wrl,    g_wr_lo);

    // --- splits ---
    {
        const int n4_0 = (N0 * D0) / 4, n4_1 = (N1 * D1) / 4;
        convert_x_kernel<<<(n4_0 + 255) / 256, 256>>>(x0, n4_0, x0h, x0l);
        convert_x_kernel<<<(n4_1 + 255) / 256, 256>>>(x1, n4_1, x1h, x1l);
        convert_w_kernel<<<(256 * D0 + 255) / 256, 256>>>(W0,    D0, w0h, w0l);
        convert_w_kernel<<<(256 * D1 + 255) / 256, 256>>>(W1,    D1, w1h, w1l);
        convert_w_kernel<<<(256 * D1 + 255) / 256, 256>>>(Wres1, D1, wrh, wrl);
    }

    // --- CSR build ---
    {
        const int nb = (N0 > N1 ? N0 : N1);
        zero_counts_kernel<<<(nb + 255) / 256, 256>>>(cnt0, cnt1, nb);
    }
    hist_kernel<<<(E + 255) / 256, 256>>>(row0, E, cnt0);
    hist_kernel<<<(E + 255) / 256, 256>>>(row1, E, cnt1);
    scan2_kernel<<<2, 1024>>>(cnt0, off0, cur0, cnt1, off1, cur1, N0);
    scatter_kernel<<<(E + 255) / 256, 256>>>(row0, col0, ew0, E, cur0, edge0);
    scatter_kernel<<<(E + 255) / 256, 256>>>(row1, col1, ew1, E, cur1, edge1);

    // --- HMMA projections ---
    {
        dim3 blk(256);
        dim3 grid0(DO_DIM / 64, (N0 + 127) / 128);
        hmma_gemm<1><<<grid0, blk>>>(x0h, x0l, w0h, w0l, nullptr, nullptr,
                                     hproj0, nullptr, N0, D0);
        dim3 grid1(DO_DIM / 64, (N1 + 127) / 128);
        hmma_gemm<2><<<grid1, blk>>>(x1h, x1l, w1h, w1l, wrh, wrl,
                                     hproj1, res1, N1, D1);
    }

    // --- aggregate + layernorm ---
    {
        const int warps_per_block = 256 / 32;
        const int nb0 = (N0 + warps_per_block - 1) / warps_per_block;
        const int nb1 = (N1 + warps_per_block - 1) / warps_per_block;
        aggregate_ln_kernel<<<nb0, 256>>>(hproj0, x0,   off0, cnt0, edge0,
                                          g0, b0, out, N0);
        aggregate_ln_kernel<<<nb1, 256>>>(hproj1, res1, off1, cnt1, edge1,
                                          g1, b1, out + (size_t)N0 * DO_DIM, N1);
    }
}

// round 4
// speedup vs baseline: 1.9683x; 1.2725x over previous
#include <cuda_runtime.h>
#include <cuda_bf16.h>
#include <cuda_fp16.h>
#include <cstdint>

// ---------------------------------------------------------------------------
// Shapes: N0 = N1 = 50000, D0 = 256, D1 = 512, DO = 256, E = 1600000
// ---------------------------------------------------------------------------
#define MAX_N   50000
#define MAX_E   1600000
#define DO_DIM  256
#define LN_EPS  1e-5f
#define NBLK    ((MAX_N + 255) / 256)      // 196 scan blocks

// ---------------------------------------------------------------------------
// Device scratch (static — no allocations allowed)
// ---------------------------------------------------------------------------
__device__ __align__(16) __half g_hproj0[MAX_N * DO_DIM];   // fp16 gather source
__device__ __align__(16) __half g_hproj1[MAX_N * DO_DIM];
__device__ __align__(16) float  g_res1  [MAX_N * DO_DIM];   // fp32 residual

__device__ int   g_cnt0[MAX_N],  g_cnt1[MAX_N];
__device__ int   g_off0[MAX_N],  g_off1[MAX_N];
__device__ int   g_cur0[MAX_N],  g_cur1[MAX_N];
__device__ int   g_bsum[2 * 256];                            // scan block sums
__device__ int2  g_edge0[MAX_E], g_edge1[MAX_E];

// W transposed + split: [N=256][K] row-major bf16
__device__ __align__(16) __nv_bfloat16 g_w0_hi[256 * 256], g_w0_lo[256 * 256];
__device__ __align__(16) __nv_bfloat16 g_w1_hi[256 * 512], g_w1_lo[256 * 512];
__device__ __align__(16) __nv_bfloat16 g_wr_hi[256 * 512], g_wr_lo[256 * 512];

// ---------------------------------------------------------------------------
// PTX helpers — only non-suffixed instructions (compute_103-safe)
// ---------------------------------------------------------------------------
__device__ __forceinline__ uint32_t smem_u32(const void* p) {
    uint32_t a;
    asm("{ .reg .u64 t; cvta.to.shared.u64 t, %1; cvt.u32.u64 %0, t; }"
        : "=r"(a) : "l"(p));
    return a;
}

#define LDSM_X4(r0, r1, r2, r3, addr)                                        \
    asm volatile("ldmatrix.sync.aligned.m8n8.x4.shared.b16 {%0,%1,%2,%3}, [%4];" \
        : "=r"(r0), "=r"(r1), "=r"(r2), "=r"(r3) : "r"(addr))

#define MMA_BF16(d, a0, a1, a2, a3, b0, b1)                                  \
    asm volatile("mma.sync.aligned.m16n8k16.row.col.f32.bf16.bf16.f32 "      \
        "{%0,%1,%2,%3},{%4,%5,%6,%7},{%8,%9},{%0,%1,%2,%3};"                 \
        : "+f"((d)[0]), "+f"((d)[1]), "+f"((d)[2]), "+f"((d)[3])             \
        : "r"(a0), "r"(a1), "r"(a2), "r"(a3), "r"(b0), "r"(b1))

// ---------------------------------------------------------------------------
// HMMA bf16-split GEMM, in-kernel A split, term-fused per K-chunk.
//   C0 (fp16) = A @ B0^T ; [NB==2] C1 (fp32) = A @ B1^T
// Block: 128(M) x 64(N), K-chunk 32, double-buffered dynamic smem, 8 warps.
// Stage layout (bytes): Ahi[0,10240) Alo[10240,20480)
//                       B[jj] hi at 20480+jj*10240, lo at +5120
// ---------------------------------------------------------------------------
template <int NB>
__global__ __launch_bounds__(256)
void hmma_gemm(const float* __restrict__ A,
               const __nv_bfloat16* __restrict__ B0h,
               const __nv_bfloat16* __restrict__ B0l,
               const __nv_bfloat16* __restrict__ B1h,
               const __nv_bfloat16* __restrict__ B1l,
               __half* __restrict__ C0, float* __restrict__ C1,
               int M, int K)
{
    constexpr int APAD = 40;
    constexpr int STAGE = 20480 + NB * 10240;
    extern __shared__ char smem[];

    const int tid  = threadIdx.x;
    const int lane = tid & 31;
    const int wid  = tid >> 5;
    const int wm   = wid >> 1;                   // 0..3  (M)
    const int wn   = wid & 1;                    // 0..1  (N)
    const int row0 = blockIdx.y * 128;
    const int col0 = blockIdx.x * 64;

    const int NC = K >> 5;                       // K-chunks

    const __nv_bfloat16* Bh[2] = {B0h, B1h};
    const __nv_bfloat16* Bl[2] = {B0l, B1l};

    float acc[NB][2][4][4];
    #pragma unroll
    for (int jj = 0; jj < NB; jj++)
        #pragma unroll
        for (int i = 0; i < 2; i++)
            #pragma unroll
            for (int q = 0; q < 4; q++)
                #pragma unroll
                for (int v = 0; v < 4; v++) acc[jj][i][q][v] = 0.f;

    // staging registers
    float4 ra[4];
    uint4  rb[NB][2];
    const int a_r  = tid >> 3;                   // base row group for A (x4 passes)
    const int a_c4 = tid & 7;                    // 4-float granule 0..7
    const int b_r  = tid >> 2;                   // 0..63
    const int b_g  = tid & 3;                    // 16B granule

    auto gload = [&](int c) {
        const int kk = c << 5;
        #pragma unroll
        for (int i = 0; i < 4; i++) {
            const int r  = i * 32 + a_r;
            const int gr = row0 + r;
            ra[i] = make_float4(0.f, 0.f, 0.f, 0.f);
            if (gr < M)
                ra[i] = *reinterpret_cast<const float4*>(
                    &A[(size_t)gr * K + kk + a_c4 * 4]);
        }
        #pragma unroll
        for (int jj = 0; jj < NB; jj++) {
            rb[jj][0] = *reinterpret_cast<const uint4*>(
                &Bh[jj][(size_t)(col0 + b_r) * K + kk + b_g * 8]);
            rb[jj][1] = *reinterpret_cast<const uint4*>(
                &Bl[jj][(size_t)(col0 + b_r) * K + kk + b_g * 8]);
        }
    };

    auto sstore = [&](int buf) {
        char* st = smem + buf * STAGE;
        #pragma unroll
        for (int i = 0; i < 4; i++) {
            const int r = i * 32 + a_r;
            const float f[4] = {ra[i].x, ra[i].y, ra[i].z, ra[i].w};
            __nv_bfloat16 h[4], l[4];
            #pragma unroll
            for (int k = 0; k < 4; k++) {
                h[k] = __float2bfloat16(f[k]);
                l[k] = __float2bfloat16(f[k] - __bfloat162float(h[k]));
            }
            uint2 hv, lv;
            hv.x = ((uint32_t)__bfloat16_as_ushort(h[1]) << 16) | __bfloat16_as_ushort(h[0]);
            hv.y = ((uint32_t)__bfloat16_as_ushort(h[3]) << 16) | __bfloat16_as_ushort(h[2]);
            lv.x = ((uint32_t)__bfloat16_as_ushort(l[1]) << 16) | __bfloat16_as_ushort(l[0]);
            lv.y = ((uint32_t)__bfloat16_as_ushort(l[3]) << 16) | __bfloat16_as_ushort(l[2]);
            const uint32_t off = (uint32_t)(r * APAD + a_c4 * 4) * 2u;
            *reinterpret_cast<uint2*>(st + off)         = hv;
            *reinterpret_cast<uint2*>(st + 10240 + off) = lv;
        }
        #pragma unroll
        for (int jj = 0; jj < NB; jj++) {
            const uint32_t off = (uint32_t)(b_r * APAD + b_g * 8) * 2u;
            *reinterpret_cast<uint4*>(st + 20480 + jj * 10240 + off)        = rb[jj][0];
            *reinterpret_cast<uint4*>(st + 20480 + jj * 10240 + 5120 + off) = rb[jj][1];
        }
    };

    const uint32_t smem_base = smem_u32(smem);

    auto compute = [&](int buf) {
        const uint32_t st = smem_base + buf * STAGE;
        #pragma unroll
        for (int j = 0; j < 2; j++) {            // two k16 halves of the 32-chunk
            uint32_t afh[2][4], afl[2][4];
            #pragma unroll
            for (int i = 0; i < 2; i++) {
                const uint32_t eoff = 2u * ((wm * 32 + i * 16 + (lane & 15)) * APAD +
                                            j * 16 + (lane >> 4) * 8);
                LDSM_X4(afh[i][0], afh[i][1], afh[i][2], afh[i][3], st + eoff);
                LDSM_X4(afl[i][0], afl[i][1], afl[i][2], afl[i][3], st + 10240 + eoff);
            }
            #pragma unroll
            for (int jj = 0; jj < NB; jj++) {
                uint32_t bh[2][4], bl[2][4];
                #pragma unroll
                for (int p = 0; p < 2; p++) {
                    const uint32_t eoff = 2u * ((wn * 32 + p * 16 + (lane & 15)) * APAD +
                                                j * 16 + (lane >> 4) * 8);
                    const uint32_t bb = st + 20480 + jj * 10240 + eoff;
                    LDSM_X4(bh[p][0], bh[p][1], bh[p][2], bh[p][3], bb);
                    LDSM_X4(bl[p][0], bl[p][1], bl[p][2], bl[p][3], bb + 5120);
                }
                #pragma unroll
                for (int i = 0; i < 2; i++)
                    #pragma unroll
                    for (int q = 0; q < 4; q++) {
                        const int p = q >> 1, s = q & 1;
                        MMA_BF16(acc[jj][i][q],
                                 afh[i][0], afh[i][1], afh[i][2], afh[i][3],
                                 bh[p][s], bh[p][s + 2]);
                        MMA_BF16(acc[jj][i][q],
                                 afh[i][0], afh[i][1], afh[i][2], afh[i][3],
                                 bl[p][s], bl[p][s + 2]);
                        MMA_BF16(acc[jj][i][q],
                                 afl[i][0], afl[i][1], afl[i][2], afl[i][3],
                                 bh[p][s], bh[p][s + 2]);
                    }
            }
        }
    };

    gload(0);
    sstore(0);
    __syncthreads();

    for (int c = 0; c < NC; c++) {
        const int cur = c & 1;
        const bool has_next = (c + 1 < NC);
        if (has_next) gload(c + 1);
        compute(cur);
        if (has_next) {
            sstore(cur ^ 1);
            __syncthreads();
        }
    }

    // ---- epilogue ----
    #pragma unroll
    for (int i = 0; i < 2; i++) {
        const int r = row0 + wm * 32 + i * 16 + (lane >> 2);
        #pragma unroll
        for (int q = 0; q < 4; q++) {
            const int cc = col0 + wn * 32 + q * 8 + (lane & 3) * 2;
            if (r < M)
                *reinterpret_cast<__half2*>(&C0[(size_t)r * DO_DIM + cc]) =
                    __floats2half2_rn(acc[0][i][q][0], acc[0][i][q][1]);
            if (r + 8 < M)
                *reinterpret_cast<__half2*>(&C0[(size_t)(r + 8) * DO_DIM + cc]) =
                    __floats2half2_rn(acc[0][i][q][2], acc[0][i][q][3]);
            if (NB == 2) {
                if (r < M)
                    *reinterpret_cast<float2*>(&C1[(size_t)r * DO_DIM + cc]) =
                        make_float2(acc[1][i][q][0], acc[1][i][q][1]);
                if (r + 8 < M)
                    *reinterpret_cast<float2*>(&C1[(size_t)(r + 8) * DO_DIM + cc]) =
                        make_float2(acc[1][i][q][2], acc[1][i][q][3]);
            }
        }
    }
}

// ---------------------------------------------------------------------------
// W [K][256] fp32 -> W^T hi/lo [256][K] bf16
// ---------------------------------------------------------------------------
__global__ void convert_w_kernel(const float* __restrict__ W, int K,
                                 __nv_bfloat16* __restrict__ hi,
                                 __nv_bfloat16* __restrict__ lo)
{
    const int idx = blockIdx.x * blockDim.x + threadIdx.x;
    if (idx >= 256 * K) return;
    const int n = idx & 255;
    const int k = idx >> 8;
    const float v = W[(size_t)k * 256 + n];
    const __nv_bfloat16 h = __float2bfloat16(v);
    hi[(size_t)n * K + k] = h;
    lo[(size_t)n * K + k] = __float2bfloat16(v - __bfloat162float(h));
}

// ---------------------------------------------------------------------------
// CSR construction
// ---------------------------------------------------------------------------
__global__ void zero_counts_kernel(int* __restrict__ c0, int* __restrict__ c1, int n)
{
    int i = blockIdx.x * blockDim.x + threadIdx.x;
    if (i < n) { c0[i] = 0; c1[i] = 0; }
}

__global__ void hist_kernel(const int* __restrict__ row, int e, int* __restrict__ cnt)
{
    int i = blockIdx.x * blockDim.x + threadIdx.x;
    if (i < e) atomicAdd(&cnt[row[i]], 1);
}

// block-wide exclusive scan of v (256 threads); returns exclusive prefix
__device__ __forceinline__ int block_exscan256(int v, int tid, int* total)
{
    __shared__ int ws[8];
    const int lane = tid & 31, wid = tid >> 5;
    int x = v;
    #pragma unroll
    for (int d = 1; d < 32; d <<= 1) {
        int y = __shfl_up_sync(0xffffffffu, x, d);
        if (lane >= d) x += y;
    }
    if (lane == 31) ws[wid] = x;
    __syncthreads();
    if (wid == 0 && lane < 8) {
        int y = ws[lane];
        #pragma unroll
        for (int d = 1; d < 8; d <<= 1) {
            int z = __shfl_up_sync(0xffu, y, d);
            if (lane >= d) y += z;
        }
        ws[lane] = y;
    }
    __syncthreads();
    const int warp_off = (wid > 0) ? ws[wid - 1] : 0;
    *total = ws[7];
    return warp_off + x - v;
}

__global__ void block_sums_kernel(const int* __restrict__ cA, const int* __restrict__ cB,
                                  int n, int* __restrict__ bsums)
{
    const int* cnt = blockIdx.y ? cB : cA;
    const int idx = blockIdx.x * 256 + threadIdx.x;
    int v = (idx < n) ? cnt[idx] : 0;
    int total;
    block_exscan256(v, threadIdx.x, &total);
    if (threadIdx.x == 0) bsums[blockIdx.y * 256 + blockIdx.x] = total;
}

__global__ void scan_tops_kernel(int* __restrict__ bsums, int nb)
{
    int* b = bsums + blockIdx.x * 256;
    const int tid = threadIdx.x;
    int v = (tid < nb) ? b[tid] : 0;
    int total;
    const int e = block_exscan256(v, tid, &total);
    if (tid < nb) b[tid] = e;
}

__global__ void scan_final_kernel(const int* __restrict__ cA, const int* __restrict__ cB,
                                  int n, const int* __restrict__ bsums,
                                  int* __restrict__ oA, int* __restrict__ uA,
                                  int* __restrict__ oB, int* __restrict__ uB)
{
    const int* cnt = blockIdx.y ? cB : cA;
    int* offs      = blockIdx.y ? oB : oA;
    int* cursor    = blockIdx.y ? uB : uA;
    const int idx  = blockIdx.x * 256 + threadIdx.x;
    int v = (idx < n) ? cnt[idx] : 0;
    int total;
    const int e = block_exscan256(v, threadIdx.x, &total) +
                  bsums[blockIdx.y * 256 + blockIdx.x];
    if (idx < n) { offs[idx] = e; cursor[idx] = e; }
}

__global__ void scatter_kernel(const int* __restrict__ row, const int* __restrict__ col,
                               const float* __restrict__ ew, int e,
                               int* __restrict__ cursor, int2* __restrict__ edges)
{
    int i = blockIdx.x * blockDim.x + threadIdx.x;
    if (i < e) {
        const int r = row[i];
        const int p = atomicAdd(&cursor[r], 1);
        edges[p] = make_int2(col[i], __float_as_int(ew[i]));
    }
}

// ---------------------------------------------------------------------------
// Aggregation + fused LayerNorm. One warp per output row, fp16 gather.
// ---------------------------------------------------------------------------
__global__ __launch_bounds__(256)
void aggregate_ln_kernel(const __half* __restrict__ hproj,
                         const float*  __restrict__ resid,
                         const int*    __restrict__ offs,
                         const int*    __restrict__ cnt,
                         const int2*   __restrict__ edges,
                         const float*  __restrict__ gamma,
                         const float*  __restrict__ beta,
                         float* __restrict__ out, int nrows)
{
    const int warp_id = (blockIdx.x * blockDim.x + threadIdx.x) >> 5;
    if (warp_id >= nrows) return;
    const int lane   = threadIdx.x & 31;
    const int base_c = lane * 8;

    const int start = offs[warp_id];
    const int n     = cnt[warp_id];

    const float4* rp = reinterpret_cast<const float4*>(
        resid + (size_t)warp_id * DO_DIM + base_c);
    float4 a0 = rp[0];
    float4 a1 = rp[1];

    for (int e = 0; e < n; e++) {
        const int2 ed = edges[start + e];
        const float w = __int_as_float(ed.y);
        const uint4 hv = *(reinterpret_cast<const uint4*>(
            hproj + (size_t)ed.x * DO_DIM) + lane);
        const __half2* hh = reinterpret_cast<const __half2*>(&hv);
        float2 f;
        f = __half22float2(hh[0]); a0.x += w * f.x; a0.y += w * f.y;
        f = __half22float2(hh[1]); a0.z += w * f.x; a0.w += w * f.y;
        f = __half22float2(hh[2]); a1.x += w * f.x; a1.y += w * f.y;
        f = __half22float2(hh[3]); a1.z += w * f.x; a1.w += w * f.y;
    }

    float s  = a0.x + a0.y + a0.z + a0.w + a1.x + a1.y + a1.z + a1.w;
    float s2 = a0.x*a0.x + a0.y*a0.y + a0.z*a0.z + a0.w*a0.w
             + a1.x*a1.x + a1.y*a1.y + a1.z*a1.z + a1.w*a1.w;
    #pragma unroll
    for (int d = 16; d > 0; d >>= 1) {
        s  += __shfl_xor_sync(0xffffffffu, s,  d);
        s2 += __shfl_xor_sync(0xffffffffu, s2, d);
    }
    const float mu  = s * (1.f / DO_DIM);
    const float var = s2 * (1.f / DO_DIM) - mu * mu;
    const float inv = rsqrtf(var + LN_EPS);

    const float4 gv0 = *reinterpret_cast<const float4*>(&gamma[base_c]);
    const float4 gv1 = *reinterpret_cast<const float4*>(&gamma[base_c + 4]);
    const float4 bv0 = *reinterpret_cast<const float4*>(&beta [base_c]);
    const float4 bv1 = *reinterpret_cast<const float4*>(&beta [base_c + 4]);

    float4 o0, o1;
    o0.x = (a0.x - mu) * inv * gv0.x + bv0.x;
    o0.y = (a0.y - mu) * inv * gv0.y + bv0.y;
    o0.z = (a0.z - mu) * inv * gv0.z + bv0.z;
    o0.w = (a0.w - mu) * inv * gv0.w + bv0.w;
    o1.x = (a1.x - mu) * inv * gv1.x + bv1.x;
    o1.y = (a1.y - mu) * inv * gv1.y + bv1.y;
    o1.z = (a1.z - mu) * inv * gv1.z + bv1.z;
    o1.w = (a1.w - mu) * inv * gv1.w + bv1.w;

    float* op = out + (size_t)warp_id * DO_DIM + base_c;
    *reinterpret_cast<float4*>(op)     = o0;
    *reinterpret_cast<float4*>(op + 4) = o1;
}

// ---------------------------------------------------------------------------
// Launch
// ---------------------------------------------------------------------------
extern "C" void kernel_launch(void* const* d_in, const int* in_sizes, int n_in,
                              void* d_out, int out_size)
{
    const float* x0    = (const float*)d_in[0];
    const float* x1    = (const float*)d_in[1];
    const float* W0    = (const float*)d_in[2];
    const float* W1    = (const float*)d_in[3];
    const float* Wres1 = (const float*)d_in[4];
    const float* g0    = (const float*)d_in[5];
    const float* b0    = (const float*)d_in[6];
    const float* g1    = (const float*)d_in[7];
    const float* b1    = (const float*)d_in[8];
    const float* ew0   = (const float*)d_in[9];
    const float* ew1   = (const float*)d_in[10];
    const int*   row0  = (const int*)d_in[11];
    const int*   col0  = (const int*)d_in[12];
    const int*   row1  = (const int*)d_in[13];
    const int*   col1  = (const int*)d_in[14];
    float* out = (float*)d_out;

    const int D0 = 256, D1 = 512;
    const int N0 = in_sizes[0] / D0;
    const int N1 = in_sizes[1] / D1;
    const int E  = in_sizes[9];

    __half *hproj0, *hproj1;
    float *res1;
    int *cnt0, *cnt1, *off0, *off1, *cur0, *cur1, *bsum;
    int2 *edge0, *edge1;
    __nv_bfloat16 *w0h, *w0l, *w1h, *w1l, *wrh, *wrl;
    cudaGetSymbolAddress((void**)&hproj0, g_hproj0);
    cudaGetSymbolAddress((void**)&hproj1, g_hproj1);
    cudaGetSymbolAddress((void**)&res1,   g_res1);
    cudaGetSymbolAddress((void**)&cnt0,   g_cnt0);
    cudaGetSymbolAddress((void**)&cnt1,   g_cnt1);
    cudaGetSymbolAddress((void**)&off0,   g_off0);
    cudaGetSymbolAddress((void**)&off1,   g_off1);
    cudaGetSymbolAddress((void**)&cur0,   g_cur0);
    cudaGetSymbolAddress((void**)&cur1,   g_cur1);
    cudaGetSymbolAddress((void**)&bsum,   g_bsum);
    cudaGetSymbolAddress((void**)&edge0,  g_edge0);
    cudaGetSymbolAddress((void**)&edge1,  g_edge1);
    cudaGetSymbolAddress((void**)&w0h,    g_w0_hi);
    cudaGetSymbolAddress((void**)&w0l,    g_w0_lo);
    cudaGetSymbolAddress((void**)&w1h,    g_w1_hi);
    cudaGetSymbolAddress((void**)&w1l,    g_w1_lo);
    cudaGetSymbolAddress((void**)&wrh,    g_wr_hi);
    cudaGetSymbolAddress((void**)&wrl,    g_wr_lo);

    // --- W splits (tiny) ---
    convert_w_kernel<<<(256 * D0 + 255) / 256, 256>>>(W0,    D0, w0h, w0l);
    convert_w_kernel<<<(256 * D1 + 255) / 256, 256>>>(W1,    D1, w1h, w1l);
    convert_w_kernel<<<(256 * D1 + 255) / 256, 256>>>(Wres1, D1, wrh, wrl);

    // --- CSR build ---
    {
        const int nb = (N0 > N1 ? N0 : N1);
        zero_counts_kernel<<<(nb + 255) / 256, 256>>>(cnt0, cnt1, nb);
    }
    hist_kernel<<<(E + 255) / 256, 256>>>(row0, E, cnt0);
    hist_kernel<<<(E + 255) / 256, 256>>>(row1, E, cnt1);
    {
        const int nblk = (N0 + 255) / 256;
        dim3 g(nblk, 2);
        block_sums_kernel<<<g, 256>>>(cnt0, cnt1, N0, bsum);
        scan_tops_kernel<<<2, 256>>>(bsum, nblk);
        scan_final_kernel<<<g, 256>>>(cnt0, cnt1, N0, bsum,
                                      off0, cur0, off1, cur1);
    }
    scatter_kernel<<<(E + 255) / 256, 256>>>(row0, col0, ew0, E, cur0, edge0);
    scatter_kernel<<<(E + 255) / 256, 256>>>(row1, col1, ew1, E, cur1, edge1);

    // --- HMMA projections (in-kernel A split) ---
    {
        constexpr int SMEM1 = 2 * (20480 + 1 * 10240);   // 61440
        constexpr int SMEM2 = 2 * (20480 + 2 * 10240);   // 81920
        cudaFuncSetAttribute(hmma_gemm<1>,
                             cudaFuncAttributeMaxDynamicSharedMemorySize, SMEM1);
        cudaFuncSetAttribute(hmma_gemm<2>,
                             cudaFuncAttributeMaxDynamicSharedMemorySize, SMEM2);
        dim3 blk(256);
        dim3 grid0(DO_DIM / 64, (N0 + 127) / 128);
        hmma_gemm<1><<<grid0, blk, SMEM1>>>(x0, w0h, w0l, nullptr, nullptr,
                                            hproj0, nullptr, N0, D0);
        dim3 grid1(DO_DIM / 64, (N1 + 127) / 128);
        hmma_gemm<2><<<grid1, blk, SMEM2>>>(x1, w1h, w1l, wrh, wrl,
                                            hproj1, res1, N1, D1);
    }

    // --- aggregate + layernorm ---
    {
        const int warps_per_block = 256 / 32;
        const int nb0 = (N0 + warps_per_block - 1) / warps_per_block;
        const int nb1 = (N1 + warps_per_block - 1) / warps_per_block;
        aggregate_ln_kernel<<<nb0, 256>>>(hproj0, x0,   off0, cnt0, edge0,
                                          g0, b0, out, N0);
        aggregate_ln_kernel<<<nb1, 256>>>(hproj1, res1, off1, cnt1, edge1,
                                          g1, b1, out + (size_t)N0 * DO_DIM, N1);
    }
}

// round 5
// speedup vs baseline: 3.1987x; 1.6251x over previous
#include <cuda_runtime.h>
#include <cuda_fp16.h>
#include <cstdint>

// ---------------------------------------------------------------------------
// Shapes: N0 = N1 = 50000, D0 = 256, D1 = 512, DO = 256, E = 1600000
// ---------------------------------------------------------------------------
#define MAX_N   50000
#define MAX_E   1600000
#define DO_DIM  256
#define LN_EPS  1e-5f

// ---------------------------------------------------------------------------
// Device scratch (static — no allocations allowed)
// ---------------------------------------------------------------------------
__device__ __align__(16) __half g_hproj0[MAX_N * DO_DIM];   // fp16 gather source
__device__ __align__(16) __half g_hproj1[MAX_N * DO_DIM];
__device__ __align__(16) float  g_res1  [MAX_N * DO_DIM];   // fp32 residual

__device__ int   g_cnt0[MAX_N],  g_cnt1[MAX_N];
__device__ int   g_off0[MAX_N],  g_off1[MAX_N];
__device__ int   g_cur0[MAX_N],  g_cur1[MAX_N];
__device__ int   g_bsum[2 * 256];
__device__ int2  g_edge0[MAX_E], g_edge1[MAX_E];

// W transposed fp16: [N=256][K] row-major
__device__ __align__(16) __half g_w0[256 * 256];
__device__ __align__(16) __half g_w1[256 * 512];
__device__ __align__(16) __half g_wr[256 * 512];

// ---------------------------------------------------------------------------
// PTX helpers — only non-suffixed instructions (compute_103-safe)
// ---------------------------------------------------------------------------
__device__ __forceinline__ uint32_t smem_u32(const void* p) {
    uint32_t a;
    asm("{ .reg .u64 t; cvta.to.shared.u64 t, %1; cvt.u32.u64 %0, t; }"
        : "=r"(a) : "l"(p));
    return a;
}

#define LDSM_X4(r0, r1, r2, r3, addr)                                        \
    asm volatile("ldmatrix.sync.aligned.m8n8.x4.shared.b16 {%0,%1,%2,%3}, [%4];" \
        : "=r"(r0), "=r"(r1), "=r"(r2), "=r"(r3) : "r"(addr))

#define MMA_F16(d, a0, a1, a2, a3, b0, b1)                                   \
    asm volatile("mma.sync.aligned.m16n8k16.row.col.f32.f16.f16.f32 "        \
        "{%0,%1,%2,%3},{%4,%5,%6,%7},{%8,%9},{%0,%1,%2,%3};"                 \
        : "+f"((d)[0]), "+f"((d)[1]), "+f"((d)[2]), "+f"((d)[3])             \
        : "r"(a0), "r"(a1), "r"(a2), "r"(a3), "r"(b0), "r"(b1))

// ---------------------------------------------------------------------------
// Single-pass fp16 HMMA GEMM, in-kernel A conversion.
//   C0 (fp16) = A @ B0^T ; [NB==2] C1 (fp32) = A @ B1^T
// Block: 128(M) x 64(N), K-chunk 32, double-buffered dynamic smem, 8 warps.
// Stage layout (halfs, APAD=40/row): A[0,10240)B ; B[jj] at 10240+jj*5120
// ---------------------------------------------------------------------------
template <int NB>
__global__ __launch_bounds__(256)
void hmma_gemm(const float* __restrict__ A,
               const __half* __restrict__ B0,
               const __half* __restrict__ B1,
               __half* __restrict__ C0, float* __restrict__ C1,
               int M, int K)
{
    constexpr int APAD  = 40;
    constexpr int STAGE = 10240 + NB * 5120;      // bytes
    extern __shared__ char smem[];

    const int tid  = threadIdx.x;
    const int lane = tid & 31;
    const int wid  = tid >> 5;
    const int wm   = wid >> 1;                    // 0..3 (M)
    const int wn   = wid & 1;                     // 0..1 (N)
    const int row0 = blockIdx.y * 128;
    const int col0 = blockIdx.x * 64;

    const int NC = K >> 5;

    const __half* Bp[2] = {B0, B1};

    float acc[NB][2][4][4];
    #pragma unroll
    for (int jj = 0; jj < NB; jj++)
        #pragma unroll
        for (int i = 0; i < 2; i++)
            #pragma unroll
            for (int q = 0; q < 4; q++)
                #pragma unroll
                for (int v = 0; v < 4; v++) acc[jj][i][q][v] = 0.f;

    float4 ra[4];
    uint4  rb[NB];
    const int a_r  = tid >> 3;                    // 0..31
    const int a_c4 = tid & 7;                     // 4-float granule
    const int b_r  = tid >> 2;                    // 0..63
    const int b_g  = tid & 3;                     // 16B granule

    auto gload = [&](int c) {
        const int kk = c << 5;
        #pragma unroll
        for (int i = 0; i < 4; i++) {
            const int gr = row0 + i * 32 + a_r;
            ra[i] = make_float4(0.f, 0.f, 0.f, 0.f);
            if (gr < M)
                ra[i] = *reinterpret_cast<const float4*>(
                    &A[(size_t)gr * K + kk + a_c4 * 4]);
        }
        #pragma unroll
        for (int jj = 0; jj < NB; jj++)
            rb[jj] = *reinterpret_cast<const uint4*>(
                &Bp[jj][(size_t)(col0 + b_r) * K + kk + b_g * 8]);
    };

    auto sstore = [&](int buf) {
        char* st = smem + buf * STAGE;
        #pragma unroll
        for (int i = 0; i < 4; i++) {
            const int r = i * 32 + a_r;
            __half2 h01 = __floats2half2_rn(ra[i].x, ra[i].y);
            __half2 h23 = __floats2half2_rn(ra[i].z, ra[i].w);
            uint2 hv;
            hv.x = *reinterpret_cast<uint32_t*>(&h01);
            hv.y = *reinterpret_cast<uint32_t*>(&h23);
            const uint32_t off = (uint32_t)(r * APAD + a_c4 * 4) * 2u;
            *reinterpret_cast<uint2*>(st + off) = hv;
        }
        #pragma unroll
        for (int jj = 0; jj < NB; jj++) {
            const uint32_t off = (uint32_t)(b_r * APAD + b_g * 8) * 2u;
            *reinterpret_cast<uint4*>(st + 10240 + jj * 5120 + off) = rb[jj];
        }
    };

    const uint32_t smem_base = smem_u32(smem);

    auto compute = [&](int buf) {
        const uint32_t st = smem_base + buf * STAGE;
        #pragma unroll
        for (int j = 0; j < 2; j++) {             // two k16 halves
            uint32_t af[2][4];
            #pragma unroll
            for (int i = 0; i < 2; i++) {
                const uint32_t eoff = 2u * ((wm * 32 + i * 16 + (lane & 15)) * APAD +
                                            j * 16 + (lane >> 4) * 8);
                LDSM_X4(af[i][0], af[i][1], af[i][2], af[i][3], st + eoff);
            }
            #pragma unroll
            for (int jj = 0; jj < NB; jj++) {
                uint32_t bh[2][4];
                #pragma unroll
                for (int p = 0; p < 2; p++) {
                    const uint32_t eoff = 2u * ((wn * 32 + p * 16 + (lane & 15)) * APAD +
                                                j * 16 + (lane >> 4) * 8);
                    LDSM_X4(bh[p][0], bh[p][1], bh[p][2], bh[p][3],
                            st + 10240 + jj * 5120 + eoff);
                }
                #pragma unroll
                for (int i = 0; i < 2; i++)
                    #pragma unroll
                    for (int q = 0; q < 4; q++) {
                        const int p = q >> 1, s = q & 1;
                        MMA_F16(acc[jj][i][q],
                                af[i][0], af[i][1], af[i][2], af[i][3],
                                bh[p][s], bh[p][s + 2]);
                    }
            }
        }
    };

    gload(0);
    sstore(0);
    __syncthreads();

    for (int c = 0; c < NC; c++) {
        const int cur = c & 1;
        const bool has_next = (c + 1 < NC);
        if (has_next) gload(c + 1);
        compute(cur);
        if (has_next) {
            sstore(cur ^ 1);
            __syncthreads();
        }
    }

    // ---- epilogue ----
    #pragma unroll
    for (int i = 0; i < 2; i++) {
        const int r = row0 + wm * 32 + i * 16 + (lane >> 2);
        #pragma unroll
        for (int q = 0; q < 4; q++) {
            const int cc = col0 + wn * 32 + q * 8 + (lane & 3) * 2;
            if (r < M)
                *reinterpret_cast<__half2*>(&C0[(size_t)r * DO_DIM + cc]) =
                    __floats2half2_rn(acc[0][i][q][0], acc[0][i][q][1]);
            if (r + 8 < M)
                *reinterpret_cast<__half2*>(&C0[(size_t)(r + 8) * DO_DIM + cc]) =
                    __floats2half2_rn(acc[0][i][q][2], acc[0][i][q][3]);
            if (NB == 2) {
                if (r < M)
                    *reinterpret_cast<float2*>(&C1[(size_t)r * DO_DIM + cc]) =
                        make_float2(acc[1][i][q][0], acc[1][i][q][1]);
                if (r + 8 < M)
                    *reinterpret_cast<float2*>(&C1[(size_t)(r + 8) * DO_DIM + cc]) =
                        make_float2(acc[1][i][q][2], acc[1][i][q][3]);
            }
        }
    }
}

// ---------------------------------------------------------------------------
// W [K][256] fp32 -> W^T fp16 [256][K]; 3 matrices in one launch (blockIdx.y)
// ---------------------------------------------------------------------------
__global__ void convert_w_kernel(const float* __restrict__ W0,
                                 const float* __restrict__ W1,
                                 const float* __restrict__ Wr,
                                 __half* __restrict__ o0,
                                 __half* __restrict__ o1,
                                 __half* __restrict__ oR)
{
    const int which = blockIdx.y;
    const float* W = (which == 0) ? W0 : (which == 1) ? W1 : Wr;
    __half* o      = (which == 0) ? o0 : (which == 1) ? o1 : oR;
    const int K    = (which == 0) ? 256 : 512;
    const int idx  = blockIdx.x * blockDim.x + threadIdx.x;
    if (idx >= 256 * K) return;
    const int n = idx & 255;
    const int k = idx >> 8;
    o[(size_t)n * K + k] = __float2half_rn(W[(size_t)k * 256 + n]);
}

// ---------------------------------------------------------------------------
// CSR construction
// ---------------------------------------------------------------------------
__global__ void zero_counts_kernel(int* __restrict__ c0, int* __restrict__ c1, int n)
{
    int i = blockIdx.x * blockDim.x + threadIdx.x;
    if (i < n) { c0[i] = 0; c1[i] = 0; }
}

__global__ void hist2_kernel(const int* __restrict__ rowA, int* __restrict__ cntA,
                             const int* __restrict__ rowB, int* __restrict__ cntB,
                             int e)
{
    const int* row = blockIdx.y ? rowB : rowA;
    int* cnt       = blockIdx.y ? cntB : cntA;
    int i = blockIdx.x * blockDim.x + threadIdx.x;
    if (i < e) atomicAdd(&cnt[row[i]], 1);
}

__device__ __forceinline__ int block_exscan256(int v, int tid, int* total)
{
    __shared__ int ws[8];
    const int lane = tid & 31, wid = tid >> 5;
    int x = v;
    #pragma unroll
    for (int d = 1; d < 32; d <<= 1) {
        int y = __shfl_up_sync(0xffffffffu, x, d);
        if (lane >= d) x += y;
    }
    if (lane == 31) ws[wid] = x;
    __syncthreads();
    if (wid == 0 && lane < 8) {
        int y = ws[lane];
        #pragma unroll
        for (int d = 1; d < 8; d <<= 1) {
            int z = __shfl_up_sync(0xffu, y, d);
            if (lane >= d) y += z;
        }
        ws[lane] = y;
    }
    __syncthreads();
    const int warp_off = (wid > 0) ? ws[wid - 1] : 0;
    *total = ws[7];
    return warp_off + x - v;
}

__global__ void block_sums_kernel(const int* __restrict__ cA, const int* __restrict__ cB,
                                  int n, int* __restrict__ bsums)
{
    const int* cnt = blockIdx.y ? cB : cA;
    const int idx = blockIdx.x * 256 + threadIdx.x;
    int v = (idx < n) ? cnt[idx] : 0;
    int total;
    block_exscan256(v, threadIdx.x, &total);
    if (threadIdx.x == 0) bsums[blockIdx.y * 256 + blockIdx.x] = total;
}

__global__ void scan_tops_kernel(int* __restrict__ bsums, int nb)
{
    int* b = bsums + blockIdx.x * 256;
    const int tid = threadIdx.x;
    int v = (tid < nb) ? b[tid] : 0;
    int total;
    const int e = block_exscan256(v, tid, &total);
    if (tid < nb) b[tid] = e;
}

__global__ void scan_final_kernel(const int* __restrict__ cA, const int* __restrict__ cB,
                                  int n, const int* __restrict__ bsums,
                                  int* __restrict__ oA, int* __restrict__ uA,
                                  int* __restrict__ oB, int* __restrict__ uB)
{
    const int* cnt = blockIdx.y ? cB : cA;
    int* offs      = blockIdx.y ? oB : oA;
    int* cursor    = blockIdx.y ? uB : uA;
    const int idx  = blockIdx.x * 256 + threadIdx.x;
    int v = (idx < n) ? cnt[idx] : 0;
    int total;
    const int e = block_exscan256(v, threadIdx.x, &total) +
                  bsums[blockIdx.y * 256 + blockIdx.x];
    if (idx < n) { offs[idx] = e; cursor[idx] = e; }
}

__global__ void scatter2_kernel(const int* __restrict__ rowA, const int* __restrict__ colA,
                                const float* __restrict__ ewA, int* __restrict__ curA,
                                int2* __restrict__ edgA,
                                const int* __restrict__ rowB, const int* __restrict__ colB,
                                const float* __restrict__ ewB, int* __restrict__ curB,
                                int2* __restrict__ edgB, int e)
{
    const int* row = blockIdx.y ? rowB : rowA;
    const int* col = blockIdx.y ? colB : colA;
    const float* ew = blockIdx.y ? ewB : ewA;
    int* cursor     = blockIdx.y ? curB : curA;
    int2* edges     = blockIdx.y ? edgB : edgA;
    int i = blockIdx.x * blockDim.x + threadIdx.x;
    if (i < e) {
        const int r = row[i];
        const int p = atomicAdd(&cursor[r], 1);
        edges[p] = make_int2(col[i], __float_as_int(ew[i]));
    }
}

// ---------------------------------------------------------------------------
// Aggregation + fused LayerNorm, both graphs in one launch (blockIdx.y).
// One warp per output row; 4-way unrolled gather for MLP.
// ---------------------------------------------------------------------------
__global__ __launch_bounds__(256)
void aggregate_ln_kernel(const __half* __restrict__ hpA, const float* __restrict__ rsA,
                         const int* __restrict__ offA, const int* __restrict__ cntA,
                         const int2* __restrict__ edgA,
                         const float* __restrict__ gA, const float* __restrict__ bA,
                         const __half* __restrict__ hpB, const float* __restrict__ rsB,
                         const int* __restrict__ offB, const int* __restrict__ cntB,
                         const int2* __restrict__ edgB,
                         const float* __restrict__ gB, const float* __restrict__ bB,
                         float* __restrict__ out, int nrows)
{
    const int which = blockIdx.y;
    const __half* hproj = which ? hpB : hpA;
    const float* resid  = which ? rsB : rsA;
    const int* offs     = which ? offB : offA;
    const int* cnt      = which ? cntB : cntA;
    const int2* edges   = which ? edgB : edgA;
    const float* gamma  = which ? gB : gA;
    const float* beta   = which ? bB : bA;
    float* o            = out + (size_t)which * nrows * DO_DIM;

    const int warp_id = (blockIdx.x * blockDim.x + threadIdx.x) >> 5;
    if (warp_id >= nrows) return;
    const int lane   = threadIdx.x & 31;
    const int base_c = lane * 8;

    const int start = offs[warp_id];
    const int n     = cnt[warp_id];
    const int2* ep  = edges + start;

    const float4* rp = reinterpret_cast<const float4*>(
        resid + (size_t)warp_id * DO_DIM + base_c);
    float4 a0 = rp[0];
    float4 a1 = rp[1];

    #define ACC_EDGE(ed) do {                                                \
        const float w = __int_as_float((ed).y);                              \
        const uint4 hv = *(reinterpret_cast<const uint4*>(                   \
            hproj + (size_t)(ed).x * DO_DIM) + lane);                        \
        const __half2* hh = reinterpret_cast<const __half2*>(&hv);           \
        float2 f;                                                            \
        f = __half22float2(hh[0]); a0.x += w * f.x; a0.y += w * f.y;         \
        f = __half22float2(hh[1]); a0.z += w * f.x; a0.w += w * f.y;         \
        f = __half22float2(hh[2]); a1.x += w * f.x; a1.y += w * f.y;         \
        f = __half22float2(hh[3]); a1.z += w * f.x; a1.w += w * f.y;         \
    } while (0)

    int e = 0;
    for (; e + 4 <= n; e += 4) {
        const int2 e0 = ep[e], e1 = ep[e + 1], e2 = ep[e + 2], e3 = ep[e + 3];
        const uint4 h0 = *(reinterpret_cast<const uint4*>(hproj + (size_t)e0.x * DO_DIM) + lane);
        const uint4 h1 = *(reinterpret_cast<const uint4*>(hproj + (size_t)e1.x * DO_DIM) + lane);
        const uint4 h2 = *(reinterpret_cast<const uint4*>(hproj + (size_t)e2.x * DO_DIM) + lane);
        const uint4 h3 = *(reinterpret_cast<const uint4*>(hproj + (size_t)e3.x * DO_DIM) + lane);
        const uint4  hvv[4] = {h0, h1, h2, h3};
        const float  ww[4]  = {__int_as_float(e0.y), __int_as_float(e1.y),
                               __int_as_float(e2.y), __int_as_float(e3.y)};
        #pragma unroll
        for (int u = 0; u < 4; u++) {
            const __half2* hh = reinterpret_cast<const __half2*>(&hvv[u]);
            const float w = ww[u];
            float2 f;
            f = __half22float2(hh[0]); a0.x += w * f.x; a0.y += w * f.y;
            f = __half22float2(hh[1]); a0.z += w * f.x; a0.w += w * f.y;
            f = __half22float2(hh[2]); a1.x += w * f.x; a1.y += w * f.y;
            f = __half22float2(hh[3]); a1.z += w * f.x; a1.w += w * f.y;
        }
    }
    for (; e < n; e++) {
        const int2 ed = ep[e];
        ACC_EDGE(ed);
    }
    #undef ACC_EDGE

    float s  = a0.x + a0.y + a0.z + a0.w + a1.x + a1.y + a1.z + a1.w;
    float s2 = a0.x*a0.x + a0.y*a0.y + a0.z*a0.z + a0.w*a0.w
             + a1.x*a1.x + a1.y*a1.y + a1.z*a1.z + a1.w*a1.w;
    #pragma unroll
    for (int d = 16; d > 0; d >>= 1) {
        s  += __shfl_xor_sync(0xffffffffu, s,  d);
        s2 += __shfl_xor_sync(0xffffffffu, s2, d);
    }
    const float mu  = s * (1.f / DO_DIM);
    const float var = s2 * (1.f / DO_DIM) - mu * mu;
    const float inv = rsqrtf(var + LN_EPS);

    const float4 gv0 = *reinterpret_cast<const float4*>(&gamma[base_c]);
    const float4 gv1 = *reinterpret_cast<const float4*>(&gamma[base_c + 4]);
    const float4 bv0 = *reinterpret_cast<const float4*>(&beta [base_c]);
    const float4 bv1 = *reinterpret_cast<const float4*>(&beta [base_c + 4]);

    float4 o0, o1;
    o0.x = (a0.x - mu) * inv * gv0.x + bv0.x;
    o0.y = (a0.y - mu) * inv * gv0.y + bv0.y;
    o0.z = (a0.z - mu) * inv * gv0.z + bv0.z;
    o0.w = (a0.w - mu) * inv * gv0.w + bv0.w;
    o1.x = (a1.x - mu) * inv * gv1.x + bv1.x;
    o1.y = (a1.y - mu) * inv * gv1.y + bv1.y;
    o1.z = (a1.z - mu) * inv * gv1.z + bv1.z;
    o1.w = (a1.w - mu) * inv * gv1.w + bv1.w;

    float* op = o + (size_t)warp_id * DO_DIM + base_c;
    *reinterpret_cast<float4*>(op)     = o0;
    *reinterpret_cast<float4*>(op + 4) = o1;
}

// ---------------------------------------------------------------------------
// Launch
// ---------------------------------------------------------------------------
extern "C" void kernel_launch(void* const* d_in, const int* in_sizes, int n_in,
                              void* d_out, int out_size)
{
    const float* x0    = (const float*)d_in[0];
    const float* x1    = (const float*)d_in[1];
    const float* W0    = (const float*)d_in[2];
    const float* W1    = (const float*)d_in[3];
    const float* Wres1 = (const float*)d_in[4];
    const float* g0    = (const float*)d_in[5];
    const float* b0    = (const float*)d_in[6];
    const float* g1    = (const float*)d_in[7];
    const float* b1    = (const float*)d_in[8];
    const float* ew0   = (const float*)d_in[9];
    const float* ew1   = (const float*)d_in[10];
    const int*   row0  = (const int*)d_in[11];
    const int*   col0  = (const int*)d_in[12];
    const int*   row1  = (const int*)d_in[13];
    const int*   col1  = (const int*)d_in[14];
    float* out = (float*)d_out;

    const int D0 = 256, D1 = 512;
    const int N0 = in_sizes[0] / D0;
    const int N1 = in_sizes[1] / D1;
    const int E  = in_sizes[9];

    __half *hproj0, *hproj1, *w0, *w1, *wr;
    float *res1;
    int *cnt0, *cnt1, *off0, *off1, *cur0, *cur1, *bsum;
    int2 *edge0, *edge1;
    cudaGetSymbolAddress((void**)&hproj0, g_hproj0);
    cudaGetSymbolAddress((void**)&hproj1, g_hproj1);
    cudaGetSymbolAddress((void**)&res1,   g_res1);
    cudaGetSymbolAddress((void**)&cnt0,   g_cnt0);
    cudaGetSymbolAddress((void**)&cnt1,   g_cnt1);
    cudaGetSymbolAddress((void**)&off0,   g_off0);
    cudaGetSymbolAddress((void**)&off1,   g_off1);
    cudaGetSymbolAddress((void**)&cur0,   g_cur0);
    cudaGetSymbolAddress((void**)&cur1,   g_cur1);
    cudaGetSymbolAddress((void**)&bsum,   g_bsum);
    cudaGetSymbolAddress((void**)&edge0,  g_edge0);
    cudaGetSymbolAddress((void**)&edge1,  g_edge1);
    cudaGetSymbolAddress((void**)&w0,     g_w0);
    cudaGetSymbolAddress((void**)&w1,     g_w1);
    cudaGetSymbolAddress((void**)&wr,     g_wr);

    // --- W transpose+fp16 (one launch) ---
    {
        dim3 g((256 * 512 + 255) / 256, 3);
        convert_w_kernel<<<g, 256>>>(W0, W1, Wres1, w0, w1, wr);
    }

    // --- CSR build ---
    {
        const int nb = (N0 > N1 ? N0 : N1);
        zero_counts_kernel<<<(nb + 255) / 256, 256>>>(cnt0, cnt1, nb);
    }
    {
        dim3 g((E + 255) / 256, 2);
        hist2_kernel<<<g, 256>>>(row0, cnt0, row1, cnt1, E);
    }
    {
        const int nblk = (N0 + 255) / 256;
        dim3 g(nblk, 2);
        block_sums_kernel<<<g, 256>>>(cnt0, cnt1, N0, bsum);
        scan_tops_kernel<<<2, 256>>>(bsum, nblk);
        scan_final_kernel<<<g, 256>>>(cnt0, cnt1, N0, bsum,
                                      off0, cur0, off1, cur1);
    }
    {
        dim3 g((E + 255) / 256, 2);
        scatter2_kernel<<<g, 256>>>(row0, col0, ew0, cur0, edge0,
                                    row1, col1, ew1, cur1, edge1, E);
    }

    // --- fp16 HMMA projections ---
    {
        constexpr int SMEM1 = 2 * (10240 + 1 * 5120);   // 30720
        constexpr int SMEM2 = 2 * (10240 + 2 * 5120);   // 40960
        cudaFuncSetAttribute(hmma_gemm<1>,
                             cudaFuncAttributeMaxDynamicSharedMemorySize, SMEM1);
        cudaFuncSetAttribute(hmma_gemm<2>,
                             cudaFuncAttributeMaxDynamicSharedMemorySize, SMEM2);
        dim3 blk(256);
        dim3 grid0(DO_DIM / 64, (N0 + 127) / 128);
        hmma_gemm<1><<<grid0, blk, SMEM1>>>(x0, w0, nullptr, hproj0, nullptr, N0, D0);
        dim3 grid1(DO_DIM / 64, (N1 + 127) / 128);
        hmma_gemm<2><<<grid1, blk, SMEM2>>>(x1, w1, wr, hproj1, res1, N1, D1);
    }

    // --- aggregate + layernorm (both graphs, one launch) ---
    {
        const int warps_per_block = 256 / 32;
        const int nb = (N0 + warps_per_block - 1) / warps_per_block;
        dim3 g(nb, 2);
        aggregate_ln_kernel<<<g, 256>>>(hproj0, x0,   off0, cnt0, edge0, g0, b0,
                                        hproj1, res1, off1, cnt1, edge1, g1, b1,
                                        out, N0);
    }
}